// round 14
// baseline (speedup 1.0000x reference)
#include <cuda_runtime.h>
#include <cuda_bf16.h>
#include <cstdint>

// Problem constants
#define BB 32
#define SV 4096
#define SQ 1152
#define DD 128
#define FD 96
#define NS 4                  // power sums S1..S4
#define CH 16                 // s-chunks in v pass
#define ROWS (SV / CH)        // 256 rows per chunk (128KB)
#define NPOOL (SQ / 12 * DD)
#define VBLOCKS (CH * BB)     // 512
#define QB_PER_B 8
#define QBLOCKS (BB * QB_PER_B)    // 256
#define P1GRID (VBLOCKS + QBLOCKS) // 768
#define NPROD (CH + QB_PER_B)      // 24 producers per batch

// TMA pipeline
#define STAGES 4
#define TROWS 16
#define TILE_BYTES (TROWS * DD * 4)   // 8192
#define NTILES (ROWS / TROWS)         // 16

// Scratch (no allocations allowed)
__device__ float g_part[CH * BB * NS * DD];
__device__ float g_qpool[BB * NPOOL];
__device__ float g_qs[BB * DD];
__device__ float g_att0[BB * DD];
__device__ float g_pI[BB * FD];
__device__ float g_L[BB], g_sa[BB], g_sa2[BB];
__device__ int   g_cb[BB];   // per-batch producer completions (reset by k_tail)

// ---- tiny PTX helpers ----
__device__ __forceinline__ uint32_t s2u(const void* p) {
    uint32_t a;
    asm("{ .reg .u64 t; cvta.to.shared.u64 t, %1; cvt.u32.u64 %0, t; }" : "=r"(a) : "l"(p));
    return a;
}
__device__ __forceinline__ void mbar_init(uint32_t a, uint32_t cnt) {
    asm volatile("mbarrier.init.shared.b64 [%0], %1;" :: "r"(a), "r"(cnt) : "memory");
}
__device__ __forceinline__ void mbar_expect(uint32_t a, uint32_t bytes) {
    asm volatile("mbarrier.arrive.expect_tx.shared.b64 _, [%0], %1;" :: "r"(a), "r"(bytes) : "memory");
}
__device__ __forceinline__ void bulk_g2s(uint32_t dst, const void* src, uint32_t bytes, uint32_t mbar) {
    asm volatile("cp.async.bulk.shared::cluster.global.mbarrier::complete_tx::bytes [%0], [%1], %2, [%3];"
                 :: "r"(dst), "l"(src), "r"(bytes), "r"(mbar) : "memory");
}
__device__ __forceinline__ void mbar_wait(uint32_t a, uint32_t parity) {
    asm volatile(
        "{\n\t"
        ".reg .pred P1;\n\t"
        "WAIT_LOOP_%=:\n\t"
        "mbarrier.try_wait.parity.acquire.cta.shared::cta.b64 P1, [%0], %1, 0x989680;\n\t"
        "@P1 bra.uni WAIT_DONE_%=;\n\t"
        "bra.uni WAIT_LOOP_%=;\n\t"
        "WAIT_DONE_%=:\n\t"
        "}"
        :: "r"(a), "r"(parity) : "memory");
}

struct SolveSmem {
    float sS[NS][DD];
    float sqs[DD];
    float shm[3], shb[3];
    float sred[8];
    float sred5[8][5];
    float spf[2][FD];
    float sumq;
};

// ---------------------------------------------------------------------------
// K1: pass1 (v via TMA bulk-copy pipeline; q via proven LDG path)
//     + inline per-batch solve by the last producer (R13 proven).
// ---------------------------------------------------------------------------
__global__ void __launch_bounds__(256, 6)
k_pass1(const float* __restrict__ v, const float* __restrict__ q,
        const float* __restrict__ hmat, const float* __restrict__ hbias) {
    __shared__ __align__(128) char s_buf[STAGES * TILE_BYTES];   // 32KB, multi-purpose
    __shared__ __align__(8) unsigned long long s_mbar[STAGES];
    __shared__ int s_last;
    int t = threadIdx.x;
    int b;

    if (blockIdx.x >= VBLOCKS) {
        // ---- q part: TWO kg-groups (16 complete k-rows), R12 verbatim ----
        int qb = blockIdx.x - VBLOCKS;
        b = qb / QB_PER_B;
        int kg0 = (qb % QB_PER_B) * 2;
        float* sp = (float*)s_buf;
        #pragma unroll
        for (int g = 0; g < 2; g++) {
            int kg = kg0 + g;
            const float4* p = (const float4*)(q + (size_t)b * SQ * DD) + (size_t)kg * 2304;
            #pragma unroll
            for (int j = 0; j < 3; j++) {
                int pidx = t + j * 256;
                const float4* pp = p + pidx * 3;
                float4 a = pp[0], c = pp[1], e = pp[2];
                float s = ((a.x + a.y) + (a.z + a.w))
                        + ((c.x + c.y) + (c.z + c.w))
                        + ((e.x + e.y) + (e.z + e.w));
                sp[pidx] = s;
                g_qpool[(size_t)b * NPOOL + kg * 768 + pidx] = s;
            }
            __syncthreads();
            if (t < 8) {
                float acc = 0.f;
                #pragma unroll
                for (int f = 0; f < 96; f++) acc += sp[t * 96 + f];
                g_qs[b * DD + kg * 8 + t] = acc;
            }
            __syncthreads();
        }
    } else {
        // ---- v power sums S1..S4 via 4-stage TMA bulk pipeline ----
        int chunk = blockIdx.x & (CH - 1);
        b = blockIdx.x / CH;
        int lane = t & 31, w = t >> 5;
        const char* gsrc = (const char*)(v + ((size_t)b * SV + (size_t)chunk * ROWS) * DD);
        uint32_t sb = s2u(s_buf);
        uint32_t mb = s2u(s_mbar);

        if (t == 0) {
            #pragma unroll
            for (int s = 0; s < STAGES; s++) mbar_init(mb + 8 * s, 1);
        }
        __syncthreads();

        if (t == 0) {
            #pragma unroll
            for (int i = 0; i < STAGES - 1; i++) {
                mbar_expect(mb + 8 * i, TILE_BYTES);
                bulk_g2s(sb + i * TILE_BYTES, gsrc + (size_t)i * TILE_BYTES, TILE_BYTES, mb + 8 * i);
            }
        }

        float s1[4] = {0,0,0,0}, s2[4] = {0,0,0,0}, s3[4] = {0,0,0,0}, s4[4] = {0,0,0,0};

        for (int i = 0; i < NTILES; i++) {
            int s = i & (STAGES - 1);
            if (t == 0 && i + STAGES - 1 < NTILES) {
                int j = i + STAGES - 1, sj = j & (STAGES - 1);
                mbar_expect(mb + 8 * sj, TILE_BYTES);
                bulk_g2s(sb + sj * TILE_BYTES, gsrc + (size_t)j * TILE_BYTES, TILE_BYTES, mb + 8 * sj);
            }
            mbar_wait(mb + 8 * s, (i >> 2) & 1);

            const float4* tp = (const float4*)(s_buf + s * TILE_BYTES);
            float4 x0 = tp[w * 32 + lane];          // global row 16i + w
            float4 x1 = tp[(w + 8) * 32 + lane];    // global row 16i + w + 8
            float a0[4] = {x0.x, x0.y, x0.z, x0.w};
            #pragma unroll
            for (int j = 0; j < 4; j++) {
                float a = a0[j];
                float a2 = a * a;
                s1[j] += a;
                s2[j] += a2;
                s3[j] = fmaf(a2, a, s3[j]);
                s4[j] = fmaf(a2, a2, s4[j]);
            }
            float a1[4] = {x1.x, x1.y, x1.z, x1.w};
            #pragma unroll
            for (int j = 0; j < 4; j++) {
                float a = a1[j];
                float a2 = a * a;
                s1[j] += a;
                s2[j] += a2;
                s3[j] = fmaf(a2, a, s3[j]);
                s4[j] = fmaf(a2, a2, s4[j]);
            }
            __syncthreads();   // stage s free for reuse
        }

        // reduce (sh aliased onto the now-idle tile buffer)
        float (*sh)[NS][DD] = (float (*)[NS][DD])s_buf;
        int d0 = lane * 4;
        #pragma unroll
        for (int j = 0; j < 4; j++) {
            sh[w][0][d0 + j] = s1[j];
            sh[w][1][d0 + j] = s2[j];
            sh[w][2][d0 + j] = s3[j];
            sh[w][3][d0 + j] = s4[j];
        }
        __syncthreads();
        #pragma unroll
        for (int idx = t; idx < NS * DD; idx += 256) {
            int k = idx >> 7, d = idx & 127;
            float acc = 0.f;
            #pragma unroll
            for (int ww = 0; ww < 8; ww++) acc += sh[ww][k][d];
            g_part[((chunk * BB + b) * NS + k) * DD + d] = acc;
        }
    }

    // ---- ticket: last producer of batch b runs the solve inline ----
    __threadfence();
    __syncthreads();
    if (t == 0) s_last = (atomicAdd(&g_cb[b], 1) == NPROD - 1) ? 1 : 0;
    __syncthreads();
    if (!s_last) return;
    __threadfence();

    // ================= SOLVE for batch b (R13 math verbatim) =================
    {
        SolveSmem* ss = (SolveSmem*)(s_buf + 16384);   // clear of nothing live

        #pragma unroll
        for (int idx = t; idx < NS * DD; idx += 256) {
            int k = idx >> 7, d = idx & 127;
            float acc = 0.f;
            #pragma unroll
            for (int c = 0; c < CH; c++)
                acc += __ldcg(&g_part[((c * BB + b) * NS + k) * DD + d]);
            ss->sS[k][d] = acc;
        }

        float myqs = 0.f;
        if (t < DD) { myqs = __ldcg(&g_qs[b * DD + t]); ss->sqs[t] = myqs; }

        if (t < 3) {
            float a = 0.f;
            for (int x = 0; x < FD; x++) a += hmat[t * FD + x];
            ss->shm[t] = a;
            ss->shb[t] = hbias[t];
        }
        __syncthreads();

        {
            float val = (t < DD) ? myqs : 0.f;
            #pragma unroll
            for (int o = 16; o; o >>= 1) val += __shfl_down_sync(0xffffffffu, val, o);
            if ((t & 31) == 0) ss->sred[t >> 5] = val;
            __syncthreads();
            if (t == 0) {
                float s = 0.f;
                #pragma unroll
                for (int i = 0; i < 8; i++) s += ss->sred[i];
                ss->sumq = s;
            }
            __syncthreads();
        }
        float sumq = ss->sumq;

        float e0 = 0.f, e1 = 0.f, e2 = 0.f, S1v = 0.f, r2 = 0.f, r3 = 0.f;
        if (t < DD) {
            int d = t;
            float S1 = ss->sS[0][d], S2 = ss->sS[1][d], S3 = ss->sS[2][d], S4 = ss->sS[3][d];
            S1v = S1;
            const float* vb = v + (size_t)b * SV * DD + d;
            float v0 = vb[0], v1 = vb[DD], v2 = vb[2 * DD];
            #pragma unroll
            for (int c = 0; c < 3; c++) {
                float A  = ss->shm[c] * sumq;
                float Bc = ss->shb[c];
                float n2 = A * A * S2 + 2.f * A * Bc * S1 + (float)SV * Bc * Bc;
                float al = A * rsqrtf(n2);
                float Z = (float)SV
                    + al * (S1 + al * (0.5f * S2 + al * ((1.f/6.f) * S3
                    + al * (1.f/24.f) * S4)));
                float iZ = 1.f / Z;
                e0 += __expf(al * v0) * iZ;
                e1 += __expf(al * v1) * iZ;
                e2 += __expf(al * v2) * iZ;
            }
            g_att0[b * DD + t] = e0;
            r2 = e1 * ss->sqs[t];
            r3 = e2 * ss->sqs[t];
        }

        {
            float r[5] = {e0, e0 * e0, r2, r3, S1v};
            #pragma unroll
            for (int o = 16; o; o >>= 1) {
                #pragma unroll
                for (int j = 0; j < 5; j++) r[j] += __shfl_down_sync(0xffffffffu, r[j], o);
            }
            if ((t & 31) == 0) {
                #pragma unroll
                for (int j = 0; j < 5; j++) ss->sred5[t >> 5][j] = r[j];
            }
            __syncthreads();
            if (t == 0) {
                float sa = 0.f, sa2 = 0.f, dot1 = 0.f, dot2 = 0.f, vs = 0.f;
                #pragma unroll
                for (int i = 0; i < 8; i++) {
                    sa += ss->sred5[i][0]; sa2 += ss->sred5[i][1];
                    dot1 += ss->sred5[i][2]; dot2 += ss->sred5[i][3];
                    vs += ss->sred5[i][4];
                }
                g_sa[b] = sa;
                g_sa2[b] = sa2;
                g_L[b] = vs * dot1 + vs * dot2;
            }
        }

        if (t < 2 * FD) {
            int f = t % FD, h = t / FD;
            float acc = 0.f;
            const float* qp = g_qpool + (size_t)b * NPOOL + f + h * 64 * FD;
            #pragma unroll 8
            for (int k = 0; k < 64; k++) acc += ss->sS[0][h * 64 + k] * __ldcg(qp + k * FD);
            ss->spf[h][f] = acc;
        }
        __syncthreads();
        if (t < FD) g_pI[b * FD + t] = (ss->spf[0][t] + ss->spf[1][t]) * (1.f / 12.f);
    }
}

// ---------------------------------------------------------------------------
// K2: finish only (96 blocks); kernel boundary is the sync (R13 proven).
// ---------------------------------------------------------------------------
__global__ void k_tail(const float* __restrict__ gamma,
                       const float* __restrict__ beta,
                       float* __restrict__ out) {
    int f = blockIdx.x;
    int t = threadIdx.x;

    __shared__ float sPI[BB], sL[BB];
    __shared__ float s_scale, s_shift;

    if (f == 0 && t < BB) g_cb[t] = 0;   // reset for next graph replay

    float m = 0.f, m2 = 0.f;
    if (t < BB) {
        float pi  = g_pI[t * FD + f];
        float L   = g_L[t];
        float sa  = g_sa[t];
        float sa2 = g_sa2[t];
        sPI[t] = pi;
        sL[t]  = L;
        m  = pi * sa + (float)DD * L;
        m2 = pi * pi * sa2 + 2.f * pi * L * sa + (float)DD * L * L;
    }
    if (t < 32) {
        #pragma unroll
        for (int o = 16; o; o >>= 1) {
            m  += __shfl_down_sync(0xffffffffu, m,  o);
            m2 += __shfl_down_sync(0xffffffffu, m2, o);
        }
        if (t == 0) {
            const float inv = 1.f / (float)(BB * DD);
            float mean = m * inv;
            float var  = m2 * inv - mean * mean;
            float scale = gamma[f] * rsqrtf(var + 1e-5f);
            s_scale = scale;
            s_shift = beta[f] - mean * scale;
        }
    }
    __syncthreads();
    float scale = s_scale, shift = s_shift;

    if (t < DD) {
        int d = t;
        #pragma unroll 8
        for (int b = 0; b < BB; b++) {
            float val = g_att0[b * DD + d] * sPI[b] + sL[b];
            out[((size_t)b * FD + f) * DD + d] = val * scale + shift;
        }
    }
}

extern "C" void kernel_launch(void* const* d_in, const int* in_sizes, int n_in,
                              void* d_out, int out_size) {
    const float* q     = (const float*)d_in[0];
    const float* v     = (const float*)d_in[1];
    const float* hmat  = (const float*)d_in[2];
    const float* hbias = (const float*)d_in[3];
    const float* gamma = (const float*)d_in[4];
    const float* beta  = (const float*)d_in[5];
    float* out = (float*)d_out;

    k_pass1<<<P1GRID, 256>>>(v, q, hmat, hbias);
    k_tail<<<FD, 128>>>(gamma, beta, out);
}